// round 15
// baseline (speedup 1.0000x reference)
#include <cuda_runtime.h>
#include <cuda_bf16.h>

// ---------------- problem constants ----------------
#define C_CL   40000
#define NSLOT  (2 * C_CL)          // fg/bg slot per cluster
#define FS     92                  // 91 feature sums + count
#define MT     128                 // points per CTA
#define NTHR   256

// ---------------- static device scratch ----------------
__device__ __align__(16) float g_sums[(size_t)NSLOT * FS];     // 29.4 MB
__device__ __align__(16) __nv_bfloat16 g_Wbf[2 * 128 * 200];   // [pass][ch][200] bf16 hi/lo
__device__ float g_bnS[128];
__device__ float g_bnQ[128];
__device__ float g_scale[128];
__device__ float g_shift[128];

// ---------------- smem layout for k_gemm (dynamic) ----------------
#define SMEM_SOFF  0                         // 128 ints
#define SMEM_SINV  512                       // 128 floats
#define SMEM_BNS   1024                      // 128 floats
#define SMEM_BNQ   1536                      // 128 floats
#define SMEM_W     2048                      // 2*128*400 = 102400 B
#define W_PASS_STRIDE 51200
#define W_ROW_STRIDE  400
#define SMEM_A     104448                    // 4 x 16384 (stage0:{AH,AL}, stage1:{AH,AL})
#define A_STAGE    32768
#define A_LO       16384
#define SMEM_TOTAL (104448 + 65536)          // 169984 B

__device__ __forceinline__ unsigned smem_u32(const void* p) {
    unsigned a;
    asm("{ .reg .u64 t; cvta.to.shared.u64 t, %1; cvt.u32.u64 %0, t; }" : "=r"(a) : "l"(p));
    return a;
}
__device__ __forceinline__ void ldsm_x4(unsigned* r, unsigned addr) {
    asm volatile("ldmatrix.sync.aligned.m8n8.x4.shared.b16 {%0,%1,%2,%3}, [%4];"
                 : "=r"(r[0]), "=r"(r[1]), "=r"(r[2]), "=r"(r[3]) : "r"(addr));
}
__device__ __forceinline__ void mma_bf16(float* d, const unsigned* a, unsigned b0, unsigned b1) {
    asm volatile(
        "mma.sync.aligned.m16n8k16.row.col.f32.bf16.bf16.f32 "
        "{%0,%1,%2,%3}, {%4,%5,%6,%7}, {%8,%9}, {%0,%1,%2,%3};"
        : "+f"(d[0]), "+f"(d[1]), "+f"(d[2]), "+f"(d[3])
        : "r"(a[0]), "r"(a[1]), "r"(a[2]), "r"(a[3]), "r"(b0), "r"(b1));
}
__device__ __forceinline__ void red_v4(float* p, float a, float b, float c, float d) {
    asm volatile("red.global.add.v4.f32 [%0], {%1, %2, %3, %4};"
                 :: "l"(p), "f"(a), "f"(b), "f"(c), "f"(d) : "memory");
}
__device__ __forceinline__ unsigned pack_bf16x2(float lo, float hi) {
    unsigned r;
    asm("cvt.rn.bf16x2.f32 %0, %1, %2;" : "=r"(r) : "f"(hi), "f"(lo));
    return r;
}

// ---------------- small kernels ----------------
__global__ void k_zero() {
    int i = blockIdx.x * blockDim.x + threadIdx.x;
    int n4 = (NSLOT * FS) / 4;
    if (i < n4) ((float4*)g_sums)[i] = make_float4(0.f, 0.f, 0.f, 0.f);
    if (i < 128) { g_bnS[i] = 0.0f; g_bnQ[i] = 0.0f; }
}

// one warp per point: 23 x red.v4 into the point's (cluster, fg/bg) slot
__global__ void k_accum(const float* __restrict__ feat, const float* __restrict__ logi,
                        const float* __restrict__ pts, const float* __restrict__ proj,
                        const int* __restrict__ cidx, const int* __restrict__ fg, int n) {
    int gt = blockIdx.x * blockDim.x + threadIdx.x;
    int w = gt >> 5, lane = gt & 31;
    if (w >= n) return;
    int ci = 0, f = 0;
    if (lane == 0) { ci = cidx[w]; f = (fg[w] != 0) ? 1 : 0; }
    ci = __shfl_sync(0xffffffffu, ci, 0);
    f  = __shfl_sync(0xffffffffu, f, 0);
    if (lane >= 23) return;
    float* dst = g_sums + (size_t)(ci * 2 + (f ? 0 : 1)) * FS + lane * 4;
    float4 v;
    if (lane < 16)      v = *(const float4*)(feat + (size_t)w * 64 + lane * 4);
    else if (lane < 21) v = *(const float4*)(logi + (size_t)w * 20 + (lane - 16) * 4);
    else if (lane == 21) v = *(const float4*)(pts + (size_t)w * 4);
    else {
        const float* pr = proj + (size_t)w * 3;
        v = make_float4(pr[0], pr[1], pr[2], 1.0f);
    }
    red_v4(dst, v.x, v.y, v.z, v.w);
}

// W as bf16 hi/lo, layout [pass][ch][200], permuted K:
// k<91: orig k; k==91: bias; 92<=k<183: orig k-1 (cluster means); else 0.
__global__ void k_prepW(const float* __restrict__ W, const float* __restrict__ b) {
    int i = blockIdx.x * blockDim.x + threadIdx.x;
    if (i >= 2 * 128 * 200) return;
    int pass = i / 25600;
    int rem = i % 25600;
    int ch = rem / 200, k = rem % 200;
    float wv;
    if (k < 91)       wv = W[ch * 182 + k];
    else if (k == 91) wv = b[ch];
    else if (k < 183) wv = W[ch * 182 + (k - 1)];
    else              wv = 0.0f;
    __nv_bfloat16 hv = __float2bfloat16_rn(wv);
    g_Wbf[i] = (pass == 0) ? hv : __float2bfloat16_rn(wv - __bfloat162float(hv));
}

// ---------------- gather helper: 32 fp32 values for (point, half, chunk) ----------
__device__ __forceinline__ void gather32(float* f, int c, int h, size_t p, size_t nsz,
                                         const float* __restrict__ feat,
                                         const float* __restrict__ logi,
                                         const float* __restrict__ pts,
                                         const float* __restrict__ proj,
                                         const float* __restrict__ mp, float inv) {
    if (p >= nsz) {
#pragma unroll
        for (int i = 0; i < 32; i++) f[i] = 0.0f;
        return;
    }
    if (c == 0) {                      // j = h*32.. : feat
        const float4* s = (const float4*)(feat + p * 64 + h * 32);
#pragma unroll
        for (int i = 0; i < 8; i++) ((float4*)f)[i] = s[i];
    } else if (c == 1) {
        if (h == 0) {                  // j 64..95
            const float4* s = (const float4*)(logi + p * 20);
#pragma unroll
            for (int i = 0; i < 5; i++) ((float4*)f)[i] = s[i];
            ((float4*)f)[5] = *(const float4*)(pts + p * 4);
            const float* pr = proj + p * 3;
            f[24] = pr[0]; f[25] = pr[1]; f[26] = pr[2];
            f[27] = 1.0f;              // bias (permuted j=91)
            float4 mv = *(const float4*)mp;
            f[28] = mv.x * inv; f[29] = mv.y * inv;
            f[30] = mv.z * inv; f[31] = mv.w * inv;
        } else {                       // j 96..127 : mean[4..35]
            const float4* s = (const float4*)(mp + 4);
#pragma unroll
            for (int i = 0; i < 8; i++) {
                float4 mv = s[i];
                f[i * 4 + 0] = mv.x * inv; f[i * 4 + 1] = mv.y * inv;
                f[i * 4 + 2] = mv.z * inv; f[i * 4 + 3] = mv.w * inv;
            }
        }
    } else {
        if (h == 0) {                  // j 128..159 : mean[36..67]
            const float4* s = (const float4*)(mp + 36);
#pragma unroll
            for (int i = 0; i < 8; i++) {
                float4 mv = s[i];
                f[i * 4 + 0] = mv.x * inv; f[i * 4 + 1] = mv.y * inv;
                f[i * 4 + 2] = mv.z * inv; f[i * 4 + 3] = mv.w * inv;
            }
        } else {                       // j 160..191 : mean[68..90] + zeros
            const float4* s = (const float4*)(mp + 68);
#pragma unroll
            for (int i = 0; i < 6; i++) {
                float4 mv = s[i];
                f[i * 4 + 0] = mv.x * inv; f[i * 4 + 1] = mv.y * inv;
                f[i * 4 + 2] = mv.z * inv; f[i * 4 + 3] = mv.w * inv;
            }
            f[23] = 0.0f;              // count slot (j=183)
#pragma unroll
            for (int i = 24; i < 32; i++) f[i] = 0.0f;
        }
    }
}

// convert 32 fp32 -> bf16 hi/lo, STS.128 into swizzled A stage
__device__ __forceinline__ void cvt_sts(const float* f, char* sm, unsigned ah_off,
                                        unsigned al_off, int p_local, int h) {
#pragma unroll
    for (int g = 0; g < 4; g++) {
        unsigned hi[4], lo[4];
#pragma unroll
        for (int e = 0; e < 4; e++) {
            float f0 = f[g * 8 + 2 * e], f1 = f[g * 8 + 2 * e + 1];
            unsigned hp = pack_bf16x2(f0, f1);
            float hf0 = __uint_as_float(hp << 16);
            float hf1 = __uint_as_float(hp & 0xffff0000u);
            lo[e] = pack_bf16x2(f0 - hf0, f1 - hf1);
            hi[e] = hp;
        }
        unsigned boff = (unsigned)p_local * 128 + (h * 32 + g * 8) * 2;
        unsigned sw = boff ^ ((boff >> 3) & 0x70);
        *(uint4*)(sm + ah_off + sw) = make_uint4(hi[0], hi[1], hi[2], hi[3]);
        *(uint4*)(sm + al_off + sw) = make_uint4(lo[0], lo[1], lo[2], lo[3]);
    }
}

// ---------------- tensor-core GEMM (mma.sync bf16, hi/lo split, pipelined) ------
// CTA: 128 points x 128 channels, 256 threads (8 warps, 4x2 grid of 32x64).
// Double-buffered A stages: gather chunk c+1 LDGs issued before MMA of chunk c.
// BN sum/sumsq fused into epilogue.
__global__ void __launch_bounds__(NTHR, 1) k_gemm(const float* __restrict__ feat,
                                                  const float* __restrict__ logi,
                                                  const float* __restrict__ pts,
                                                  const float* __restrict__ proj,
                                                  const int* __restrict__ cidx,
                                                  const int* __restrict__ fg,
                                                  float* __restrict__ out, int n) {
    extern __shared__ __align__(128) char sm[];
    unsigned smem_base = smem_u32(sm);
    int t = threadIdx.x, wid = t >> 5, lane = t & 31;
    size_t p0 = (size_t)blockIdx.x * MT;

    // stage per-point cluster slot + 1/count, init BN partials
    if (t < MT) {
        size_t p = p0 + t;
        int off = 0; float inv = 0.0f;
        if (p < (size_t)n) {
            int ci = cidx[p];
            int f = (fg[p] != 0) ? 1 : 0;
            off = (ci * 2 + (f ? 0 : 1)) * FS;
            float cnt = g_sums[off + 91];
            inv = (cnt > 0.5f) ? 1.0f / cnt : 0.0f;
        }
        ((int*)(sm + SMEM_SOFF))[t] = off;
        ((float*)(sm + SMEM_SINV))[t] = inv;
        ((float*)(sm + SMEM_BNS))[t] = 0.0f;
        ((float*)(sm + SMEM_BNQ))[t] = 0.0f;
    }
    __syncthreads();

    int p_local = t >> 1, h = t & 1;          // gather: point, 32-col half
    size_t p = p0 + p_local;
    const float* mp = g_sums + ((int*)(sm + SMEM_SOFF))[p_local];
    float inv = ((float*)(sm + SMEM_SINV))[p_local];

    // copy prepared W image (100 KB, L2-resident): overlaps with first gather
    {
        const uint4* src = (const uint4*)g_Wbf;
        uint4* dst = (uint4*)(sm + SMEM_W);
#pragma unroll
        for (int i = 0; i < 25; i++) dst[t + i * NTHR] = src[t + i * NTHR];
    }

    float f[32];
    gather32(f, 0, h, p, (size_t)n, feat, logi, pts, proj, mp, inv);
    cvt_sts(f, sm, SMEM_A, SMEM_A + A_LO, p_local, h);
    __syncthreads();

    int wm = wid & 3, wn = wid >> 2;          // warp tile: m0=wm*32, n0=wn*64
    int m0 = wm * 32, n0 = wn * 64;

    float acc[2][8][4];
#pragma unroll
    for (int mt = 0; mt < 2; mt++)
#pragma unroll
        for (int nt = 0; nt < 8; nt++)
#pragma unroll
            for (int e = 0; e < 4; e++) acc[mt][nt][e] = 0.0f;

#pragma unroll
    for (int c = 0; c < 3; c++) {
        // issue next chunk's gather LDGs before MMA of current chunk
        if (c < 2) gather32(f, c + 1, h, p, (size_t)n, feat, logi, pts, proj, mp, inv);

        unsigned stage = (unsigned)(c & 1) * A_STAGE;
        // ---- mma on current stage: 3 pass-combos x 4 ksteps ----
#pragma unroll
        for (int combo = 0; combo < 3; combo++) {
            unsigned abase = smem_base + SMEM_A + stage + ((combo == 2) ? A_LO : 0);
            unsigned wbase = smem_base + SMEM_W + ((combo == 1) ? W_PASS_STRIDE : 0);
#pragma unroll
            for (int ks = 0; ks < 4; ks++) {
                int kin = ks * 16;                       // col within chunk
                int kglob = c * 64 + kin;                // global K (0..191)
                unsigned a[2][4];
#pragma unroll
                for (int mt = 0; mt < 2; mt++) {
                    int r = m0 + mt * 16 + (lane & 15);
                    unsigned off = (unsigned)r * 128 + (kin + (lane >> 4) * 8) * 2;
                    unsigned sw = off ^ (((unsigned)(r & 7)) << 4);
                    ldsm_x4(a[mt], abase + sw);
                }
                unsigned b[4][4];
#pragma unroll
                for (int nt2 = 0; nt2 < 4; nt2++) {
                    int row = n0 + nt2 * 16 + (lane & 15);
                    unsigned addr = wbase + (unsigned)row * W_ROW_STRIDE
                                  + (kglob + (lane >> 4) * 8) * 2;
                    ldsm_x4(b[nt2], addr);
                }
#pragma unroll
                for (int mt = 0; mt < 2; mt++)
#pragma unroll
                    for (int nt2 = 0; nt2 < 4; nt2++) {
                        mma_bf16(acc[mt][nt2 * 2 + 0], a[mt], b[nt2][0], b[nt2][2]);
                        mma_bf16(acc[mt][nt2 * 2 + 1], a[mt], b[nt2][1], b[nt2][3]);
                    }
            }
        }
        if (c < 2) {
            unsigned nstage = (unsigned)((c + 1) & 1) * A_STAGE;
            cvt_sts(f, sm, SMEM_A + nstage, SMEM_A + nstage + A_LO, p_local, h);
            __syncthreads();
        }
    }

    // ---- epilogue: store D fragments + fused BN partials ----
    float bs[16], bq[16];
#pragma unroll
    for (int i = 0; i < 16; i++) { bs[i] = 0.0f; bq[i] = 0.0f; }
#pragma unroll
    for (int mt = 0; mt < 2; mt++) {
        size_t r0 = p0 + m0 + mt * 16 + (lane >> 2);
        size_t r1 = r0 + 8;
        bool v0 = r0 < (size_t)n, v1 = r1 < (size_t)n;
#pragma unroll
        for (int nt = 0; nt < 8; nt++) {
            int cb = n0 + nt * 8 + (lane & 3) * 2;
            if (v0) {
                float e0 = acc[mt][nt][0], e1 = acc[mt][nt][1];
                *(float2*)(out + r0 * 128 + cb) = make_float2(e0, e1);
                bs[nt * 2] += e0;     bq[nt * 2] += e0 * e0;
                bs[nt * 2 + 1] += e1; bq[nt * 2 + 1] += e1 * e1;
            }
            if (v1) {
                float e2 = acc[mt][nt][2], e3 = acc[mt][nt][3];
                *(float2*)(out + r1 * 128 + cb) = make_float2(e2, e3);
                bs[nt * 2] += e2;     bq[nt * 2] += e2 * e2;
                bs[nt * 2 + 1] += e3; bq[nt * 2 + 1] += e3 * e3;
            }
        }
    }
    float* bnS = (float*)(sm + SMEM_BNS);
    float* bnQ = (float*)(sm + SMEM_BNQ);
#pragma unroll
    for (int nt = 0; nt < 8; nt++) {
        int cb = n0 + nt * 8 + (lane & 3) * 2;
        atomicAdd(&bnS[cb], bs[nt * 2]);
        atomicAdd(&bnS[cb + 1], bs[nt * 2 + 1]);
        atomicAdd(&bnQ[cb], bq[nt * 2]);
        atomicAdd(&bnQ[cb + 1], bq[nt * 2 + 1]);
    }
    __syncthreads();
    if (t < 128) {
        atomicAdd(&g_bnS[t], bnS[t]);
        atomicAdd(&g_bnQ[t], bnQ[t]);
    }
}

__global__ void k_bnparam(const float* __restrict__ gamma, const float* __restrict__ beta,
                          float inv_n) {
    int c = threadIdx.x;
    float mu  = g_bnS[c] * inv_n;
    float var = fmaxf(g_bnQ[c] * inv_n - mu * mu, 0.0f);
    float s = gamma[c] * rsqrtf(var + 1e-5f);
    g_scale[c] = s;
    g_shift[c] = beta[c] - mu * s;
}

__global__ void k_apply(float* __restrict__ out, int t4) {
    __shared__ float sc[128], sh[128];
    if (threadIdx.x < 128) { sc[threadIdx.x] = g_scale[threadIdx.x]; sh[threadIdx.x] = g_shift[threadIdx.x]; }
    __syncthreads();
    int i = blockIdx.x * blockDim.x + threadIdx.x;
    if (i >= t4) return;
    int c0 = (i << 2) & 127;
    float4 v = ((float4*)out)[i];
    float a0 = fmaf(v.x, sc[c0 + 0], sh[c0 + 0]);
    float a1 = fmaf(v.y, sc[c0 + 1], sh[c0 + 1]);
    float a2 = fmaf(v.z, sc[c0 + 2], sh[c0 + 2]);
    float a3 = fmaf(v.w, sc[c0 + 3], sh[c0 + 3]);
    v.x = fmaxf(a0, 0.1f * a0);
    v.y = fmaxf(a1, 0.1f * a1);
    v.z = fmaxf(a2, 0.1f * a2);
    v.w = fmaxf(a3, 0.1f * a3);
    ((float4*)out)[i] = v;
}

// ---------------- launch ----------------
extern "C" void kernel_launch(void* const* d_in, const int* in_sizes, int n_in,
                              void* d_out, int out_size) {
    const float* pts   = (const float*)d_in[0];   // [N,4]
    const float* proj  = (const float*)d_in[1];   // [N,3]
    const float* feat  = (const float*)d_in[2];   // [N,64]
    const float* logi  = (const float*)d_in[3];   // [N,20]
    const int*   cidx  = (const int*)d_in[4];     // [N]
    const int*   fg    = (const int*)d_in[5];     // [N] nonzero == true
    const float* W     = (const float*)d_in[6];   // [128,182]
    const float* b     = (const float*)d_in[7];   // [128]
    const float* gamma = (const float*)d_in[8];   // [128]
    const float* beta  = (const float*)d_in[9];   // [128]
    float* out = (float*)d_out;

    int n = in_sizes[4];
    int nb = (n + MT - 1) / MT;

    cudaFuncSetAttribute(k_gemm, cudaFuncAttributeMaxDynamicSharedMemorySize, SMEM_TOTAL);

    k_zero  <<<((NSLOT * FS) / 4 + 255) / 256, 256>>>();
    k_accum <<<(n * 32 + 255) / 256, 256>>>(feat, logi, pts, proj, cidx, fg, n);
    k_prepW <<<(2 * 128 * 200 + 255) / 256, 256>>>(W, b);
    k_gemm  <<<nb, NTHR, SMEM_TOTAL>>>(feat, logi, pts, proj, cidx, fg, out, n);
    k_bnparam<<<1, 128>>>(gamma, beta, 1.0f / (float)n);
    int t4 = n * 32;
    k_apply <<<(t4 + 255) / 256, 256>>>(out, t4);
}

// round 16
// speedup vs baseline: 1.1513x; 1.1513x over previous
#include <cuda_runtime.h>
#include <cuda_bf16.h>

// ---------------- problem constants ----------------
#define C_CL   40000
#define NSLOT  (2 * C_CL)          // fg/bg slot per cluster
#define FS     92                  // 91 feature sums + count
#define MT     192                 // points per CTA
#define NTHR   384

// ---------------- static device scratch ----------------
__device__ __align__(16) float g_sums[(size_t)NSLOT * FS];     // 29.4 MB
__device__ __align__(16) __nv_bfloat16 g_Wbf[2 * 128 * 200];   // [pass][ch][200] bf16 hi/lo
__device__ float g_bnS[128];
__device__ float g_bnQ[128];
__device__ float g_scale[128];
__device__ float g_shift[128];

// ---------------- smem layout for k_gemm (dynamic) ----------------
#define SMEM_SOFF  0                         // 192 ints
#define SMEM_SINV  768                       // 192 floats
#define SMEM_W     1536                      // 2*128*400 = 102400 B
#define W_PASS_STRIDE 51200
#define W_ROW_STRIDE  400
#define SMEM_AH    (1536 + 102400)           // 103936 (128B aligned)
#define SMEM_AL    (SMEM_AH + MT * 128)      // +24576
#define SMEM_BNS   (SMEM_AL + MT * 128)      // 153088: 128 floats
#define SMEM_BNQ   (SMEM_BNS + 512)          // 153600: 128 floats
#define SMEM_TOTAL (SMEM_BNQ + 512)          // 154112 B

__device__ __forceinline__ unsigned smem_u32(const void* p) {
    unsigned a;
    asm("{ .reg .u64 t; cvta.to.shared.u64 t, %1; cvt.u32.u64 %0, t; }" : "=r"(a) : "l"(p));
    return a;
}
__device__ __forceinline__ void ldsm_x4(unsigned* r, unsigned addr) {
    asm volatile("ldmatrix.sync.aligned.m8n8.x4.shared.b16 {%0,%1,%2,%3}, [%4];"
                 : "=r"(r[0]), "=r"(r[1]), "=r"(r[2]), "=r"(r[3]) : "r"(addr));
}
__device__ __forceinline__ void mma_bf16(float* d, const unsigned* a, unsigned b0, unsigned b1) {
    asm volatile(
        "mma.sync.aligned.m16n8k16.row.col.f32.bf16.bf16.f32 "
        "{%0,%1,%2,%3}, {%4,%5,%6,%7}, {%8,%9}, {%0,%1,%2,%3};"
        : "+f"(d[0]), "+f"(d[1]), "+f"(d[2]), "+f"(d[3])
        : "r"(a[0]), "r"(a[1]), "r"(a[2]), "r"(a[3]), "r"(b0), "r"(b1));
}
__device__ __forceinline__ void red_v4(float* p, float a, float b, float c, float d) {
    asm volatile("red.global.add.v4.f32 [%0], {%1, %2, %3, %4};"
                 :: "l"(p), "f"(a), "f"(b), "f"(c), "f"(d) : "memory");
}
__device__ __forceinline__ unsigned pack_bf16x2(float lo, float hi) {
    unsigned r;
    asm("cvt.rn.bf16x2.f32 %0, %1, %2;" : "=r"(r) : "f"(hi), "f"(lo));
    return r;
}

// ---------------- small kernels ----------------
__global__ void k_zero() {
    int i = blockIdx.x * blockDim.x + threadIdx.x;
    int n4 = (NSLOT * FS) / 4;
    if (i < n4) ((float4*)g_sums)[i] = make_float4(0.f, 0.f, 0.f, 0.f);
    if (i < 128) { g_bnS[i] = 0.0f; g_bnQ[i] = 0.0f; }
}

// one warp per point: 23 x red.v4 into the point's (cluster, fg/bg) slot
__global__ void k_accum(const float* __restrict__ feat, const float* __restrict__ logi,
                        const float* __restrict__ pts, const float* __restrict__ proj,
                        const int* __restrict__ cidx, const int* __restrict__ fg, int n) {
    int gt = blockIdx.x * blockDim.x + threadIdx.x;
    int w = gt >> 5, lane = gt & 31;
    if (w >= n) return;
    int ci = 0, f = 0;
    if (lane == 0) { ci = cidx[w]; f = (fg[w] != 0) ? 1 : 0; }
    ci = __shfl_sync(0xffffffffu, ci, 0);
    f  = __shfl_sync(0xffffffffu, f, 0);
    if (lane >= 23) return;
    float* dst = g_sums + (size_t)(ci * 2 + (f ? 0 : 1)) * FS + lane * 4;
    float4 v;
    if (lane < 16)      v = *(const float4*)(feat + (size_t)w * 64 + lane * 4);
    else if (lane < 21) v = *(const float4*)(logi + (size_t)w * 20 + (lane - 16) * 4);
    else if (lane == 21) v = *(const float4*)(pts + (size_t)w * 4);
    else {
        const float* pr = proj + (size_t)w * 3;
        v = make_float4(pr[0], pr[1], pr[2], 1.0f);
    }
    red_v4(dst, v.x, v.y, v.z, v.w);
}

// W as bf16 hi/lo, layout [pass][ch][200], permuted K:
// k<91: orig k; k==91: bias; 92<=k<183: orig k-1 (cluster means); else 0.
__global__ void k_prepW(const float* __restrict__ W, const float* __restrict__ b) {
    int i = blockIdx.x * blockDim.x + threadIdx.x;
    if (i >= 2 * 128 * 200) return;
    int pass = i / 25600;
    int rem = i % 25600;
    int ch = rem / 200, k = rem % 200;
    float wv;
    if (k < 91)       wv = W[ch * 182 + k];
    else if (k == 91) wv = b[ch];
    else if (k < 183) wv = W[ch * 182 + (k - 1)];
    else              wv = 0.0f;
    __nv_bfloat16 hv = __float2bfloat16_rn(wv);
    g_Wbf[i] = (pass == 0) ? hv : __float2bfloat16_rn(wv - __bfloat162float(hv));
}

// ---------------- tensor-core GEMM (mma.sync bf16, hi/lo split) ----------------
// CTA: 192 points x 128 channels, 384 threads (12 warps, 6x2 warp grid of 32x64).
// 3 K-chunks of 64; per chunk: gather fp32 x -> bf16 hi/lo in smem, then
// 3 passes (AH*WH, AH*WL, AL*WH) x 4 ksteps of m16n8k16.
// BN sum/sumsq fused into the epilogue.
__global__ void __launch_bounds__(NTHR, 1) k_gemm(const float* __restrict__ feat,
                                                  const float* __restrict__ logi,
                                                  const float* __restrict__ pts,
                                                  const float* __restrict__ proj,
                                                  const int* __restrict__ cidx,
                                                  const int* __restrict__ fg,
                                                  float* __restrict__ out, int n) {
    extern __shared__ __align__(128) char sm[];
    unsigned smem_base = smem_u32(sm);
    int t = threadIdx.x, wid = t >> 5, lane = t & 31;
    size_t p0 = (size_t)blockIdx.x * MT;

    // stage per-point cluster slot + 1/count; init BN partials
    if (t < MT) {
        size_t p = p0 + t;
        int off = 0; float inv = 0.0f;
        if (p < (size_t)n) {
            int ci = cidx[p];
            int f = (fg[p] != 0) ? 1 : 0;
            off = (ci * 2 + (f ? 0 : 1)) * FS;
            float cnt = g_sums[off + 91];
            inv = (cnt > 0.5f) ? 1.0f / cnt : 0.0f;
        }
        ((int*)(sm + SMEM_SOFF))[t] = off;
        ((float*)(sm + SMEM_SINV))[t] = inv;
    }
    if (t < 128) {
        ((float*)(sm + SMEM_BNS))[t] = 0.0f;
        ((float*)(sm + SMEM_BNQ))[t] = 0.0f;
    }
    // copy prepared W image (100 KB, L2-resident)
    {
        const uint4* src = (const uint4*)g_Wbf;
        uint4* dst = (uint4*)(sm + SMEM_W);
#pragma unroll
        for (int i = 0; i < 17; i++) {
            int idx = t + i * NTHR;
            if (idx < 6400) dst[idx] = src[idx];
        }
    }
    __syncthreads();

    int p_local = t >> 1, h = t & 1;          // gather: point, 32-col half
    size_t p = p0 + p_local;
    const float* mp = g_sums + ((int*)(sm + SMEM_SOFF))[p_local];
    float inv = ((float*)(sm + SMEM_SINV))[p_local];

    int wm = wid % 6, wn = wid / 6;           // warp tile: m0=wm*32, n0=wn*64
    int m0 = wm * 32, n0 = wn * 64;

    float acc[2][8][4];
#pragma unroll
    for (int mt = 0; mt < 2; mt++)
#pragma unroll
        for (int nt = 0; nt < 8; nt++)
#pragma unroll
            for (int e = 0; e < 4; e++) acc[mt][nt][e] = 0.0f;

    for (int c = 0; c < 3; c++) {
        if (c) __syncthreads();               // prev chunk's mma done before overwrite
        // ---- gather 32 fp32 values for (point, half) of this chunk ----
        float f[32];
        if (p < (size_t)n) {
            if (c == 0) {                      // j = h*32.. : feat
                const float4* s = (const float4*)(feat + p * 64 + h * 32);
#pragma unroll
                for (int i = 0; i < 8; i++) ((float4*)f)[i] = s[i];
            } else if (c == 1) {
                if (h == 0) {                  // j 64..95
                    const float4* s = (const float4*)(logi + p * 20);
#pragma unroll
                    for (int i = 0; i < 5; i++) ((float4*)f)[i] = s[i];
                    ((float4*)f)[5] = *(const float4*)(pts + p * 4);
                    const float* pr = proj + p * 3;
                    f[24] = pr[0]; f[25] = pr[1]; f[26] = pr[2];
                    f[27] = 1.0f;              // bias (permuted j=91)
                    float4 mv = *(const float4*)mp;
                    f[28] = mv.x * inv; f[29] = mv.y * inv;
                    f[30] = mv.z * inv; f[31] = mv.w * inv;
                } else {                       // j 96..127 : mean[4..35]
                    const float4* s = (const float4*)(mp + 4);
#pragma unroll
                    for (int i = 0; i < 8; i++) {
                        float4 mv = s[i];
                        f[i * 4 + 0] = mv.x * inv; f[i * 4 + 1] = mv.y * inv;
                        f[i * 4 + 2] = mv.z * inv; f[i * 4 + 3] = mv.w * inv;
                    }
                }
            } else {
                if (h == 0) {                  // j 128..159 : mean[36..67]
                    const float4* s = (const float4*)(mp + 36);
#pragma unroll
                    for (int i = 0; i < 8; i++) {
                        float4 mv = s[i];
                        f[i * 4 + 0] = mv.x * inv; f[i * 4 + 1] = mv.y * inv;
                        f[i * 4 + 2] = mv.z * inv; f[i * 4 + 3] = mv.w * inv;
                    }
                } else {                       // j 160..191 : mean[68..90] + zeros
                    const float4* s = (const float4*)(mp + 68);
#pragma unroll
                    for (int i = 0; i < 6; i++) {
                        float4 mv = s[i];
                        f[i * 4 + 0] = mv.x * inv; f[i * 4 + 1] = mv.y * inv;
                        f[i * 4 + 2] = mv.z * inv; f[i * 4 + 3] = mv.w * inv;
                    }
                    f[23] = 0.0f;              // count slot (j=183)
#pragma unroll
                    for (int i = 24; i < 32; i++) f[i] = 0.0f;
                }
            }
        } else {
#pragma unroll
            for (int i = 0; i < 32; i++) f[i] = 0.0f;
        }

        // ---- convert to bf16 hi/lo, STS.128 into swizzled A buffers ----
#pragma unroll
        for (int g = 0; g < 4; g++) {
            unsigned hi[4], lo[4];
#pragma unroll
            for (int e = 0; e < 4; e++) {
                float f0 = f[g * 8 + 2 * e], f1 = f[g * 8 + 2 * e + 1];
                unsigned hp = pack_bf16x2(f0, f1);
                float hf0 = __uint_as_float(hp << 16);
                float hf1 = __uint_as_float(hp & 0xffff0000u);
                lo[e] = pack_bf16x2(f0 - hf0, f1 - hf1);
                hi[e] = hp;
            }
            unsigned boff = (unsigned)p_local * 128 + (h * 32 + g * 8) * 2;
            unsigned sw = boff ^ ((boff >> 3) & 0x70);
            *(uint4*)(sm + SMEM_AH + sw) = make_uint4(hi[0], hi[1], hi[2], hi[3]);
            *(uint4*)(sm + SMEM_AL + sw) = make_uint4(lo[0], lo[1], lo[2], lo[3]);
        }
        __syncthreads();

        // ---- mma: 3 pass-combos x 4 ksteps ----
#pragma unroll
        for (int combo = 0; combo < 3; combo++) {
            unsigned abase = smem_base + ((combo == 2) ? SMEM_AL : SMEM_AH);
            unsigned wbase = smem_base + SMEM_W + ((combo == 1) ? W_PASS_STRIDE : 0);
#pragma unroll
            for (int ks = 0; ks < 4; ks++) {
                int kin = ks * 16;                       // col within chunk
                int kglob = c * 64 + kin;                // global K (0..191)
                unsigned a[2][4];
#pragma unroll
                for (int mt = 0; mt < 2; mt++) {
                    int r = m0 + mt * 16 + (lane & 15);
                    unsigned off = (unsigned)r * 128 + (kin + (lane >> 4) * 8) * 2;
                    unsigned sw = off ^ (((unsigned)(r & 7)) << 4);
                    ldsm_x4(a[mt], abase + sw);
                }
                // B: non-trans ldmatrix over [channel][k] rows gives the
                // m16n8k16 row.col B fragment directly (k-pairs within lane).
                unsigned b[4][4];
#pragma unroll
                for (int nt2 = 0; nt2 < 4; nt2++) {
                    int row = n0 + nt2 * 16 + (lane & 15);
                    unsigned addr = wbase + (unsigned)row * W_ROW_STRIDE
                                  + (kglob + (lane >> 4) * 8) * 2;
                    ldsm_x4(b[nt2], addr);
                }
#pragma unroll
                for (int mt = 0; mt < 2; mt++)
#pragma unroll
                    for (int nt2 = 0; nt2 < 4; nt2++) {
                        mma_bf16(acc[mt][nt2 * 2 + 0], a[mt], b[nt2][0], b[nt2][2]);
                        mma_bf16(acc[mt][nt2 * 2 + 1], a[mt], b[nt2][1], b[nt2][3]);
                    }
            }
        }
    }

    // ---- epilogue: store D fragments + fused BN partials ----
    float bs[16], bq[16];
#pragma unroll
    for (int i = 0; i < 16; i++) { bs[i] = 0.0f; bq[i] = 0.0f; }
#pragma unroll
    for (int mt = 0; mt < 2; mt++) {
        size_t r0 = p0 + m0 + mt * 16 + (lane >> 2);
        size_t r1 = r0 + 8;
        bool v0 = r0 < (size_t)n, v1 = r1 < (size_t)n;
#pragma unroll
        for (int nt = 0; nt < 8; nt++) {
            int cb = n0 + nt * 8 + (lane & 3) * 2;
            if (v0) {
                float e0 = acc[mt][nt][0], e1 = acc[mt][nt][1];
                *(float2*)(out + r0 * 128 + cb) = make_float2(e0, e1);
                bs[nt * 2] += e0;     bq[nt * 2] += e0 * e0;
                bs[nt * 2 + 1] += e1; bq[nt * 2 + 1] += e1 * e1;
            }
            if (v1) {
                float e2 = acc[mt][nt][2], e3 = acc[mt][nt][3];
                *(float2*)(out + r1 * 128 + cb) = make_float2(e2, e3);
                bs[nt * 2] += e2;     bq[nt * 2] += e2 * e2;
                bs[nt * 2 + 1] += e3; bq[nt * 2 + 1] += e3 * e3;
            }
        }
    }
    float* bnS = (float*)(sm + SMEM_BNS);
    float* bnQ = (float*)(sm + SMEM_BNQ);
#pragma unroll
    for (int nt = 0; nt < 8; nt++) {
        int cb = n0 + nt * 8 + (lane & 3) * 2;
        atomicAdd(&bnS[cb], bs[nt * 2]);
        atomicAdd(&bnS[cb + 1], bs[nt * 2 + 1]);
        atomicAdd(&bnQ[cb], bq[nt * 2]);
        atomicAdd(&bnQ[cb + 1], bq[nt * 2 + 1]);
    }
    __syncthreads();
    if (t < 128) {
        atomicAdd(&g_bnS[t], bnS[t]);
        atomicAdd(&g_bnQ[t], bnQ[t]);
    }
}

__global__ void k_bnparam(const float* __restrict__ gamma, const float* __restrict__ beta,
                          float inv_n) {
    int c = threadIdx.x;
    float mu  = g_bnS[c] * inv_n;
    float var = fmaxf(g_bnQ[c] * inv_n - mu * mu, 0.0f);
    float s = gamma[c] * rsqrtf(var + 1e-5f);
    g_scale[c] = s;
    g_shift[c] = beta[c] - mu * s;
}

__global__ void k_apply(float* __restrict__ out, int t4) {
    __shared__ float sc[128], sh[128];
    if (threadIdx.x < 128) { sc[threadIdx.x] = g_scale[threadIdx.x]; sh[threadIdx.x] = g_shift[threadIdx.x]; }
    __syncthreads();
    int i = blockIdx.x * blockDim.x + threadIdx.x;
    if (i >= t4) return;
    int c0 = (i << 2) & 127;
    float4 v = ((float4*)out)[i];
    float a0 = fmaf(v.x, sc[c0 + 0], sh[c0 + 0]);
    float a1 = fmaf(v.y, sc[c0 + 1], sh[c0 + 1]);
    float a2 = fmaf(v.z, sc[c0 + 2], sh[c0 + 2]);
    float a3 = fmaf(v.w, sc[c0 + 3], sh[c0 + 3]);
    v.x = fmaxf(a0, 0.1f * a0);
    v.y = fmaxf(a1, 0.1f * a1);
    v.z = fmaxf(a2, 0.1f * a2);
    v.w = fmaxf(a3, 0.1f * a3);
    ((float4*)out)[i] = v;
}

// ---------------- launch ----------------
extern "C" void kernel_launch(void* const* d_in, const int* in_sizes, int n_in,
                              void* d_out, int out_size) {
    const float* pts   = (const float*)d_in[0];   // [N,4]
    const float* proj  = (const float*)d_in[1];   // [N,3]
    const float* feat  = (const float*)d_in[2];   // [N,64]
    const float* logi  = (const float*)d_in[3];   // [N,20]
    const int*   cidx  = (const int*)d_in[4];     // [N]
    const int*   fg    = (const int*)d_in[5];     // [N] nonzero == true
    const float* W     = (const float*)d_in[6];   // [128,182]
    const float* b     = (const float*)d_in[7];   // [128]
    const float* gamma = (const float*)d_in[8];   // [128]
    const float* beta  = (const float*)d_in[9];   // [128]
    float* out = (float*)d_out;

    int n = in_sizes[4];
    int nb = (n + MT - 1) / MT;

    cudaFuncSetAttribute(k_gemm, cudaFuncAttributeMaxDynamicSharedMemorySize, SMEM_TOTAL);

    k_zero  <<<((NSLOT * FS) / 4 + 255) / 256, 256>>>();
    k_accum <<<(n * 32 + 255) / 256, 256>>>(feat, logi, pts, proj, cidx, fg, n);
    k_prepW <<<(2 * 128 * 200 + 255) / 256, 256>>>(W, b);
    k_gemm  <<<nb, NTHR, SMEM_TOTAL>>>(feat, logi, pts, proj, cidx, fg, out, n);
    k_bnparam<<<1, 128>>>(gamma, beta, 1.0f / (float)n);
    int t4 = n * 32;
    k_apply <<<(t4 + 255) / 256, 256>>>(out, t4);
}

// round 17
// speedup vs baseline: 1.6879x; 1.4661x over previous
#include <cuda_runtime.h>
#include <cuda_bf16.h>

// ---------------- problem constants ----------------
#define C_CL   40000
#define NSLOT  (2 * C_CL)          // fg/bg slot per cluster
#define FS     92                  // 91 feature sums + count
#define MT     128                 // points per CTA
#define NTHR   384                 // 8 consumer warps + 4 producer warps

// ---------------- static device scratch ----------------
__device__ __align__(16) float g_sums[(size_t)NSLOT * FS];     // 29.4 MB
__device__ __align__(16) __nv_bfloat16 g_Wbf[2 * 128 * 200];   // [pass][ch][200] bf16 hi/lo
__device__ float g_bnS[128];
__device__ float g_bnQ[128];
__device__ float g_scale[128];
__device__ float g_shift[128];

// ---------------- smem layout for k_gemm (dynamic) ----------------
#define SMEM_SOFF  0                         // 128 ints
#define SMEM_SINV  512                       // 128 floats
#define SMEM_W     1024                      // 2*128*400 = 102400 B
#define W_PASS_STRIDE 51200
#define W_ROW_STRIDE  400
#define SMEM_A     (1024 + 102400)           // 103424 (128B aligned)
#define A_STAGE    32768                     // per double-buffer stage (AH+AL)
#define A_LO       16384
#define SMEM_TOTAL (103424 + 2 * A_STAGE)    // 168960 B

// named barriers: 1 = stage0 full, 2 = stage1 full, 3 = stage0 free
#define BAR_ARRIVE(id) asm volatile("bar.arrive %0, %1;" :: "r"(id), "r"(NTHR) : "memory")
#define BAR_SYNC(id)   asm volatile("bar.sync %0, %1;"   :: "r"(id), "r"(NTHR) : "memory")

__device__ __forceinline__ unsigned smem_u32(const void* p) {
    unsigned a;
    asm("{ .reg .u64 t; cvta.to.shared.u64 t, %1; cvt.u32.u64 %0, t; }" : "=r"(a) : "l"(p));
    return a;
}
__device__ __forceinline__ void ldsm_x4(unsigned* r, unsigned addr) {
    asm volatile("ldmatrix.sync.aligned.m8n8.x4.shared.b16 {%0,%1,%2,%3}, [%4];"
                 : "=r"(r[0]), "=r"(r[1]), "=r"(r[2]), "=r"(r[3]) : "r"(addr));
}
__device__ __forceinline__ void mma_bf16(float* d, const unsigned* a, unsigned b0, unsigned b1) {
    asm volatile(
        "mma.sync.aligned.m16n8k16.row.col.f32.bf16.bf16.f32 "
        "{%0,%1,%2,%3}, {%4,%5,%6,%7}, {%8,%9}, {%0,%1,%2,%3};"
        : "+f"(d[0]), "+f"(d[1]), "+f"(d[2]), "+f"(d[3])
        : "r"(a[0]), "r"(a[1]), "r"(a[2]), "r"(a[3]), "r"(b0), "r"(b1));
}
__device__ __forceinline__ void red_v4(float* p, float a, float b, float c, float d) {
    asm volatile("red.global.add.v4.f32 [%0], {%1, %2, %3, %4};"
                 :: "l"(p), "f"(a), "f"(b), "f"(c), "f"(d) : "memory");
}
__device__ __forceinline__ unsigned pack_bf16x2(float lo, float hi) {
    unsigned r;
    asm("cvt.rn.bf16x2.f32 %0, %1, %2;" : "=r"(r) : "f"(hi), "f"(lo));
    return r;
}

// ---------------- small kernels ----------------
__global__ void k_zero() {
    int i = blockIdx.x * blockDim.x + threadIdx.x;
    int n4 = (NSLOT * FS) / 4;
    if (i < n4) ((float4*)g_sums)[i] = make_float4(0.f, 0.f, 0.f, 0.f);
    if (i < 128) { g_bnS[i] = 0.0f; g_bnQ[i] = 0.0f; }
}

// one warp per point: 23 x red.v4 into the point's (cluster, fg/bg) slot
__global__ void k_accum(const float* __restrict__ feat, const float* __restrict__ logi,
                        const float* __restrict__ pts, const float* __restrict__ proj,
                        const int* __restrict__ cidx, const int* __restrict__ fg, int n) {
    int gt = blockIdx.x * blockDim.x + threadIdx.x;
    int w = gt >> 5, lane = gt & 31;
    if (w >= n) return;
    int ci = 0, f = 0;
    if (lane == 0) { ci = cidx[w]; f = (fg[w] != 0) ? 1 : 0; }
    ci = __shfl_sync(0xffffffffu, ci, 0);
    f  = __shfl_sync(0xffffffffu, f, 0);
    if (lane >= 23) return;
    float* dst = g_sums + (size_t)(ci * 2 + (f ? 0 : 1)) * FS + lane * 4;
    float4 v;
    if (lane < 16)      v = *(const float4*)(feat + (size_t)w * 64 + lane * 4);
    else if (lane < 21) v = *(const float4*)(logi + (size_t)w * 20 + (lane - 16) * 4);
    else if (lane == 21) v = *(const float4*)(pts + (size_t)w * 4);
    else {
        const float* pr = proj + (size_t)w * 3;
        v = make_float4(pr[0], pr[1], pr[2], 1.0f);
    }
    red_v4(dst, v.x, v.y, v.z, v.w);
}

// W as bf16 hi/lo, layout [pass][ch][200], permuted K:
// k<91: orig k; k==91: bias; 92<=k<183: orig k-1 (cluster means); else 0.
__global__ void k_prepW(const float* __restrict__ W, const float* __restrict__ b) {
    int i = blockIdx.x * blockDim.x + threadIdx.x;
    if (i >= 2 * 128 * 200) return;
    int pass = i / 25600;
    int rem = i % 25600;
    int ch = rem / 200, k = rem % 200;
    float wv;
    if (k < 91)       wv = W[ch * 182 + k];
    else if (k == 91) wv = b[ch];
    else if (k < 183) wv = W[ch * 182 + (k - 1)];
    else              wv = 0.0f;
    __nv_bfloat16 hv = __float2bfloat16_rn(wv);
    g_Wbf[i] = (pass == 0) ? hv : __float2bfloat16_rn(wv - __bfloat162float(hv));
}

// ---------------- gather helper: 32 fp32 values for (point, half, chunk) ----------
__device__ __forceinline__ void gather32(float* f, int c, int h, size_t p, size_t nsz,
                                         const float* __restrict__ feat,
                                         const float* __restrict__ logi,
                                         const float* __restrict__ pts,
                                         const float* __restrict__ proj,
                                         const float* __restrict__ mp, float inv) {
    if (p >= nsz) {
#pragma unroll
        for (int i = 0; i < 32; i++) f[i] = 0.0f;
        return;
    }
    if (c == 0) {                      // j = h*32.. : feat
        const float4* s = (const float4*)(feat + p * 64 + h * 32);
#pragma unroll
        for (int i = 0; i < 8; i++) ((float4*)f)[i] = s[i];
    } else if (c == 1) {
        if (h == 0) {                  // j 64..95
            const float4* s = (const float4*)(logi + p * 20);
#pragma unroll
            for (int i = 0; i < 5; i++) ((float4*)f)[i] = s[i];
            ((float4*)f)[5] = *(const float4*)(pts + p * 4);
            const float* pr = proj + p * 3;
            f[24] = pr[0]; f[25] = pr[1]; f[26] = pr[2];
            f[27] = 1.0f;              // bias (permuted j=91)
            float4 mv = *(const float4*)mp;
            f[28] = mv.x * inv; f[29] = mv.y * inv;
            f[30] = mv.z * inv; f[31] = mv.w * inv;
        } else {                       // j 96..127 : mean[4..35]
            const float4* s = (const float4*)(mp + 4);
#pragma unroll
            for (int i = 0; i < 8; i++) {
                float4 mv = s[i];
                f[i * 4 + 0] = mv.x * inv; f[i * 4 + 1] = mv.y * inv;
                f[i * 4 + 2] = mv.z * inv; f[i * 4 + 3] = mv.w * inv;
            }
        }
    } else {
        if (h == 0) {                  // j 128..159 : mean[36..67]
            const float4* s = (const float4*)(mp + 36);
#pragma unroll
            for (int i = 0; i < 8; i++) {
                float4 mv = s[i];
                f[i * 4 + 0] = mv.x * inv; f[i * 4 + 1] = mv.y * inv;
                f[i * 4 + 2] = mv.z * inv; f[i * 4 + 3] = mv.w * inv;
            }
        } else {                       // j 160..191 : mean[68..90] + zeros
            const float4* s = (const float4*)(mp + 68);
#pragma unroll
            for (int i = 0; i < 6; i++) {
                float4 mv = s[i];
                f[i * 4 + 0] = mv.x * inv; f[i * 4 + 1] = mv.y * inv;
                f[i * 4 + 2] = mv.z * inv; f[i * 4 + 3] = mv.w * inv;
            }
            f[23] = 0.0f;              // count slot (j=183)
#pragma unroll
            for (int i = 24; i < 32; i++) f[i] = 0.0f;
        }
    }
}

// convert 32 fp32 -> bf16 hi/lo, STS.128 into swizzled A stage
__device__ __forceinline__ void cvt_sts(const float* f, char* sm, unsigned ah_off,
                                        unsigned al_off, int p_local, int h) {
#pragma unroll
    for (int g = 0; g < 4; g++) {
        unsigned hi[4], lo[4];
#pragma unroll
        for (int e = 0; e < 4; e++) {
            float f0 = f[g * 8 + 2 * e], f1 = f[g * 8 + 2 * e + 1];
            unsigned hp = pack_bf16x2(f0, f1);
            float hf0 = __uint_as_float(hp << 16);
            float hf1 = __uint_as_float(hp & 0xffff0000u);
            lo[e] = pack_bf16x2(f0 - hf0, f1 - hf1);
            hi[e] = hp;
        }
        unsigned boff = (unsigned)p_local * 128 + (h * 32 + g * 8) * 2;
        unsigned sw = boff ^ ((boff >> 3) & 0x70);
        *(uint4*)(sm + ah_off + sw) = make_uint4(hi[0], hi[1], hi[2], hi[3]);
        *(uint4*)(sm + al_off + sw) = make_uint4(lo[0], lo[1], lo[2], lo[3]);
    }
}

// ---------------- warp-specialized tensor-core GEMM ----------------
// CTA: 128 points x 128 channels. Warps 0-7 = consumers (4x2 grid of 32x64
// tiles, same MMA code as the 632us kernel). Warps 8-11 = producers: gather
// fp32 x, bf16 hi/lo split, STS into double-buffered A stages. Named-barrier
// producer/consumer handshake; chunk time = max(gather, MMA) instead of sum.
__global__ void __launch_bounds__(NTHR, 1) k_gemm(const float* __restrict__ feat,
                                                  const float* __restrict__ logi,
                                                  const float* __restrict__ pts,
                                                  const float* __restrict__ proj,
                                                  const int* __restrict__ cidx,
                                                  const int* __restrict__ fg,
                                                  float* __restrict__ out, int n) {
    extern __shared__ __align__(128) char sm[];
    unsigned smem_base = smem_u32(sm);
    int t = threadIdx.x, wid = t >> 5, lane = t & 31;
    size_t p0 = (size_t)blockIdx.x * MT;

    // stage per-point cluster slot + 1/count
    if (t < MT) {
        size_t p = p0 + t;
        int off = 0; float inv = 0.0f;
        if (p < (size_t)n) {
            int ci = cidx[p];
            int f = (fg[p] != 0) ? 1 : 0;
            off = (ci * 2 + (f ? 0 : 1)) * FS;
            float cnt = g_sums[off + 91];
            inv = (cnt > 0.5f) ? 1.0f / cnt : 0.0f;
        }
        ((int*)(sm + SMEM_SOFF))[t] = off;
        ((float*)(sm + SMEM_SINV))[t] = inv;
    }
    // copy prepared W image (100 KB, L2-resident)
    {
        const uint4* src = (const uint4*)g_Wbf;
        uint4* dst = (uint4*)(sm + SMEM_W);
#pragma unroll
        for (int i = 0; i < 17; i++) {
            int idx = t + i * NTHR;
            if (idx < 6400) dst[idx] = src[idx];
        }
    }
    __syncthreads();

    if (wid >= 8) {
        // ================= producer warps (8-11), 128 threads =================
        int pt = t - 256;                         // 0..127
        // two (point, half) units per thread: u and u+128
        int u0 = pt, u1 = pt + 128;
        int pl0 = u0 >> 1, h0 = u0 & 1;
        int pl1 = u1 >> 1, h1 = u1 & 1;
        size_t pp0 = p0 + pl0, pp1 = p0 + pl1;
        const float* mp0 = g_sums + ((int*)(sm + SMEM_SOFF))[pl0];
        const float* mp1 = g_sums + ((int*)(sm + SMEM_SOFF))[pl1];
        float iv0 = ((float*)(sm + SMEM_SINV))[pl0];
        float iv1 = ((float*)(sm + SMEM_SINV))[pl1];

        for (int c = 0; c < 3; c++) {
            if (c == 2) BAR_SYNC(3);              // stage0 reused: wait consumers free it
            unsigned st = SMEM_A + (unsigned)(c & 1) * A_STAGE;
            float f[32];
            gather32(f, c, h0, pp0, (size_t)n, feat, logi, pts, proj, mp0, iv0);
            cvt_sts(f, sm, st, st + A_LO, pl0, h0);
            gather32(f, c, h1, pp1, (size_t)n, feat, logi, pts, proj, mp1, iv1);
            cvt_sts(f, sm, st, st + A_LO, pl1, h1);
            __threadfence_block();
            BAR_ARRIVE(1 + (c & 1));              // stage full
        }
    } else {
        // ================= consumer warps (0-7), 256 threads ==================
        int wm = wid & 3, wn = wid >> 2;          // warp tile: m0=wm*32, n0=wn*64
        int m0 = wm * 32, n0 = wn * 64;

        float acc[2][8][4];
#pragma unroll
        for (int mt = 0; mt < 2; mt++)
#pragma unroll
            for (int nt = 0; nt < 8; nt++)
#pragma unroll
                for (int e = 0; e < 4; e++) acc[mt][nt][e] = 0.0f;

        for (int c = 0; c < 3; c++) {
            BAR_SYNC(1 + (c & 1));                // wait stage full
            unsigned stage = SMEM_A + (unsigned)(c & 1) * A_STAGE;
#pragma unroll
            for (int combo = 0; combo < 3; combo++) {
                unsigned abase = smem_base + stage + ((combo == 2) ? A_LO : 0);
                unsigned wbase = smem_base + SMEM_W + ((combo == 1) ? W_PASS_STRIDE : 0);
#pragma unroll
                for (int ks = 0; ks < 4; ks++) {
                    int kin = ks * 16;                       // col within chunk
                    int kglob = c * 64 + kin;                // global K (0..191)
                    unsigned a[2][4];
#pragma unroll
                    for (int mt = 0; mt < 2; mt++) {
                        int r = m0 + mt * 16 + (lane & 15);
                        unsigned off = (unsigned)r * 128 + (kin + (lane >> 4) * 8) * 2;
                        unsigned sw = off ^ (((unsigned)(r & 7)) << 4);
                        ldsm_x4(a[mt], abase + sw);
                    }
                    // B: non-trans ldmatrix over [channel][k] rows gives the
                    // m16n8k16 row.col B fragment directly.
                    unsigned b[4][4];
#pragma unroll
                    for (int nt2 = 0; nt2 < 4; nt2++) {
                        int row = n0 + nt2 * 16 + (lane & 15);
                        unsigned addr = wbase + (unsigned)row * W_ROW_STRIDE
                                      + (kglob + (lane >> 4) * 8) * 2;
                        ldsm_x4(b[nt2], addr);
                    }
#pragma unroll
                    for (int mt = 0; mt < 2; mt++)
#pragma unroll
                        for (int nt2 = 0; nt2 < 4; nt2++) {
                            mma_bf16(acc[mt][nt2 * 2 + 0], a[mt], b[nt2][0], b[nt2][2]);
                            mma_bf16(acc[mt][nt2 * 2 + 1], a[mt], b[nt2][1], b[nt2][3]);
                        }
                }
            }
            if (c == 0) BAR_ARRIVE(3);            // stage0 free for chunk 2
        }

        // ---- epilogue: store D fragments ----
#pragma unroll
        for (int mt = 0; mt < 2; mt++) {
            size_t r0 = p0 + m0 + mt * 16 + (lane >> 2);
            size_t r1 = r0 + 8;
#pragma unroll
            for (int nt = 0; nt < 8; nt++) {
                int cb = n0 + nt * 8 + (lane & 3) * 2;
                if (r0 < (size_t)n)
                    *(float2*)(out + r0 * 128 + cb) = make_float2(acc[mt][nt][0], acc[mt][nt][1]);
                if (r1 < (size_t)n)
                    *(float2*)(out + r1 * 128 + cb) = make_float2(acc[mt][nt][2], acc[mt][nt][3]);
            }
        }
    }
}

// per-channel BN sums over out
__global__ void k_bnsum(const float* __restrict__ out, int n) {
    __shared__ float sS[256], sQ[256];
    int t = threadIdx.x;
    int c = t & 127;
    int r0 = blockIdx.x * 1024 + (t >> 7);
    int rend = blockIdx.x * 1024 + 1024;
    if (rend > n) rend = n;
    float s = 0.0f, q = 0.0f;
    for (int r = r0; r < rend; r += 2) {
        float v = out[(size_t)r * 128 + c];
        s += v; q += v * v;
    }
    sS[t] = s; sQ[t] = q;
    __syncthreads();
    if (t < 128) {
        atomicAdd(&g_bnS[c], sS[t] + sS[t + 128]);
        atomicAdd(&g_bnQ[c], sQ[t] + sQ[t + 128]);
    }
}

__global__ void k_bnparam(const float* __restrict__ gamma, const float* __restrict__ beta,
                          float inv_n) {
    int c = threadIdx.x;
    float mu  = g_bnS[c] * inv_n;
    float var = fmaxf(g_bnQ[c] * inv_n - mu * mu, 0.0f);
    float s = gamma[c] * rsqrtf(var + 1e-5f);
    g_scale[c] = s;
    g_shift[c] = beta[c] - mu * s;
}

__global__ void k_apply(float* __restrict__ out, int t4) {
    __shared__ float sc[128], sh[128];
    if (threadIdx.x < 128) { sc[threadIdx.x] = g_scale[threadIdx.x]; sh[threadIdx.x] = g_shift[threadIdx.x]; }
    __syncthreads();
    int i = blockIdx.x * blockDim.x + threadIdx.x;
    if (i >= t4) return;
    int c0 = (i << 2) & 127;
    float4 v = ((float4*)out)[i];
    float a0 = fmaf(v.x, sc[c0 + 0], sh[c0 + 0]);
    float a1 = fmaf(v.y, sc[c0 + 1], sh[c0 + 1]);
    float a2 = fmaf(v.z, sc[c0 + 2], sh[c0 + 2]);
    float a3 = fmaf(v.w, sc[c0 + 3], sh[c0 + 3]);
    v.x = fmaxf(a0, 0.1f * a0);
    v.y = fmaxf(a1, 0.1f * a1);
    v.z = fmaxf(a2, 0.1f * a2);
    v.w = fmaxf(a3, 0.1f * a3);
    ((float4*)out)[i] = v;
}

// ---------------- launch ----------------
extern "C" void kernel_launch(void* const* d_in, const int* in_sizes, int n_in,
                              void* d_out, int out_size) {
    const float* pts   = (const float*)d_in[0];   // [N,4]
    const float* proj  = (const float*)d_in[1];   // [N,3]
    const float* feat  = (const float*)d_in[2];   // [N,64]
    const float* logi  = (const float*)d_in[3];   // [N,20]
    const int*   cidx  = (const int*)d_in[4];     // [N]
    const int*   fg    = (const int*)d_in[5];     // [N] nonzero == true
    const float* W     = (const float*)d_in[6];   // [128,182]
    const float* b     = (const float*)d_in[7];   // [128]
    const float* gamma = (const float*)d_in[8];   // [128]
    const float* beta  = (const float*)d_in[9];   // [128]
    float* out = (float*)d_out;

    int n = in_sizes[4];
    int nb = (n + MT - 1) / MT;

    cudaFuncSetAttribute(k_gemm, cudaFuncAttributeMaxDynamicSharedMemorySize, SMEM_TOTAL);

    k_zero  <<<((NSLOT * FS) / 4 + 255) / 256, 256>>>();
    k_accum <<<(n * 32 + 255) / 256, 256>>>(feat, logi, pts, proj, cidx, fg, n);
    k_prepW <<<(2 * 128 * 200 + 255) / 256, 256>>>(W, b);
    k_gemm  <<<nb, NTHR, SMEM_TOTAL>>>(feat, logi, pts, proj, cidx, fg, out, n);
    k_bnsum <<<(n + 1023) / 1024, 256>>>(out, n);
    k_bnparam<<<1, 128>>>(gamma, beta, 1.0f / (float)n);
    int t4 = n * 32;
    k_apply <<<(t4 + 255) / 256, 256>>>(out, t4);
}